// round 1
// baseline (speedup 1.0000x reference)
#include <cuda_runtime.h>
#include <cstdint>

#define Bn 32
#define Cn 512
#define Hn 40
#define Wn 40
#define Nn 1600          // H*W
#define NCn 20
#define NOUT 25          // 1 obj + 20 cls + 4 reg
#define STRIDEF 32.0f
#define CONF_T 0.3f
#define NMS_T 0.5f

typedef unsigned long long ull;

// ---------------- scratch (device globals; no allocations allowed) ----------
__device__ float g_boxes[Bn * Nn * 4];
__device__ float g_scores[Bn * Nn];
__device__ int   g_labels[Bn * Nn];

// ---------------- f32x2 helpers (FFMA2 only reachable via PTX) --------------
__device__ __forceinline__ ull pack2(float x, float y) {
    ull r; asm("mov.b64 %0, {%1, %2};" : "=l"(r) : "f"(x), "f"(y)); return r;
}
__device__ __forceinline__ void fma2(ull& d, ull a, ull b) {
    asm("fma.rn.f32x2 %0, %1, %2, %0;" : "+l"(d) : "l"(a), "l"(b));
}
__device__ __forceinline__ float2 unpack2(ull v) {
    float2 r; asm("mov.b64 {%0, %1}, %2;" : "=f"(r.x), "=f"(r.y) : "l"(v)); return r;
}
__device__ __forceinline__ float sigmoidf_(float x) {
    return 1.0f / (1.0f + expf(-x));
}

// ---------------- Kernel A: fused head (1x1 convs) + decode -----------------
// grid: 400 blocks x 128 threads = 51200 = B*N cells, one thread per cell.
// Shared weights layout: ws[c*26 + o] (o in [0,25), slot 25 pad) so that
// consecutive output pairs (2p,2p+1) are 8B-aligned 64-bit LDS broadcasts.
extern __shared__ float smemA[];

__global__ void __launch_bounds__(128) head_kernel(
    const float* __restrict__ feat,
    const float* __restrict__ wo, const float* __restrict__ bo,
    const float* __restrict__ wc, const float* __restrict__ bc,
    const float* __restrict__ wr, const float* __restrict__ br,
    float* __restrict__ out)
{
    float* ws   = smemA;             // 512*26 floats
    float* bias = smemA + Cn * 26;   // 25 floats
    const int tid = threadIdx.x;

    for (int i = tid; i < Cn * NOUT; i += blockDim.x) {
        int c = i / NOUT, o = i - c * NOUT;
        float w;
        if (o == 0)        w = wo[c];
        else if (o <= NCn) w = wc[(o - 1) * Cn + c];
        else               w = wr[(o - 1 - NCn) * Cn + c];
        ws[c * 26 + o] = w;
    }
    if (tid < NOUT) {
        float v;
        if (tid == 0)        v = bo[0];
        else if (tid <= NCn) v = bc[tid - 1];
        else                 v = br[tid - 1 - NCn];
        bias[tid] = v;
    }
    __syncthreads();

    const int gcell = blockIdx.x * 128 + tid;
    const int b = gcell / Nn;
    const int n = gcell - b * Nn;
    const float* fp = feat + (size_t)b * Cn * Nn + n;
    const ull* wp = (const ull*)ws;   // pair p of column c at wp[c*13 + p]

    ull acc[12];
#pragma unroll
    for (int p = 0; p < 12; p++) acc[p] = 0ULL;
    float acc24 = 0.0f;

#pragma unroll 1
    for (int c0 = 0; c0 < Cn; c0 += 16) {
        float v[16];
#pragma unroll
        for (int u = 0; u < 16; u++) v[u] = fp[(c0 + u) * Nn];
#pragma unroll
        for (int u = 0; u < 16; u++) {
            ull vv = pack2(v[u], v[u]);
            int base = (c0 + u) * 13;
#pragma unroll
            for (int p = 0; p < 12; p++) fma2(acc[p], vv, wp[base + p]);
            acc24 = fmaf(v[u], ws[(c0 + u) * 26 + 24], acc24);
        }
    }

    float r[25];
#pragma unroll
    for (int p = 0; p < 12; p++) {
        float2 t = unpack2(acc[p]);
        r[2 * p]     = t.x + bias[2 * p];
        r[2 * p + 1] = t.y + bias[2 * p + 1];
    }
    r[24] = acc24 + bias[24];

    // scores / labels: argmax over class logits == argmax over sqrt(sig*sig)
    float sig_obj = sigmoidf_(r[0]);
    float best = r[1]; int lab = 0;
#pragma unroll
    for (int k = 1; k < NCn; k++) {
        if (r[1 + k] > best) { best = r[1 + k]; lab = k; }
    }
    float score = sqrtf(sig_obj * sigmoidf_(best));

    // decode boxes
    float gx = (float)(n % Wn), gy = (float)(n / Wn);
    float cx = (sigmoidf_(r[21]) + gx) * STRIDEF;
    float cy = (sigmoidf_(r[22]) + gy) * STRIDEF;
    float bw = expf(r[23]) * STRIDEF;
    float bh = expf(r[24]) * STRIDEF;

    int idx = b * Nn + n;
    g_boxes[idx * 4 + 0] = cx - bw * 0.5f;
    g_boxes[idx * 4 + 1] = cy - bh * 0.5f;
    g_boxes[idx * 4 + 2] = cx + bw * 0.5f;
    g_boxes[idx * 4 + 3] = cy + bh * 0.5f;
    g_scores[idx] = score;
    g_labels[idx] = lab;
    // labels output region: offset B*N*5, as float
    out[Bn * Nn * 5 + idx] = (float)lab;
}

// ---------------- Kernel B: per-(batch,class) NMS + output compose ----------
// Cross-class pairs never suppress in the reference, so per-class NMS with
// order = stable argsort(-scores) restricted to the class is exact.
__global__ void __launch_bounds__(256) nms_kernel(float* __restrict__ out)
{
    __shared__ ull sk[2048];                 // (~score_bits)<<32 | cell_idx
    __shared__ float sx1[Nn], sy1[Nn], sx2[Nn], sy2[Nn];
    __shared__ unsigned char skeep[Nn];
    __shared__ int cnt;

    const int cls = blockIdx.x, b = blockIdx.y;
    const int tid = threadIdx.x;
    const int T = 256;

    if (tid == 0) cnt = 0;
    __syncthreads();

    // compact cells of this class
    for (int n = tid; n < Nn; n += T) {
        int idx = b * Nn + n;
        if (g_labels[idx] == cls) {
            int pos = atomicAdd(&cnt, 1);
            unsigned int sb = __float_as_uint(g_scores[idx]); // scores > 0
            sk[pos] = ((ull)(~sb) << 32) | (unsigned)n;       // desc score, asc idx
        }
    }
    __syncthreads();
    const int M = cnt;
    int P = 2; while (P < M) P <<= 1;
    for (int i = M + tid; i < P; i += T) sk[i] = ~0ULL;
    __syncthreads();

    // bitonic sort ascending on 64-bit keys
    for (int k = 2; k <= P; k <<= 1) {
        for (int j = k >> 1; j > 0; j >>= 1) {
            for (int i = tid; i < P; i += T) {
                int x = i ^ j;
                if (x > i) {
                    bool up = ((i & k) == 0);
                    ull a = sk[i], c = sk[x];
                    if ((a > c) == up) { sk[i] = c; sk[x] = a; }
                }
            }
            __syncthreads();
        }
    }

    // gather boxes in sorted order; init keep = conf mask
    for (int t = tid; t < M; t += T) {
        int n = (int)(sk[t] & 0xFFFFFFFFULL);
        int idx = b * Nn + n;
        sx1[t] = g_boxes[idx * 4 + 0];
        sy1[t] = g_boxes[idx * 4 + 1];
        sx2[t] = g_boxes[idx * 4 + 2];
        sy2[t] = g_boxes[idx * 4 + 3];
        float s = __uint_as_float(~(unsigned)(sk[t] >> 32));
        skeep[t] = (s > CONF_T) ? 1 : 0;
    }
    __syncthreads();

    // greedy serial suppression (exact match of reference fori_loop per class)
    for (int i = 0; i < M; i++) {
        if (skeep[i]) {
            float ax1 = sx1[i], ay1 = sy1[i], ax2 = sx2[i], ay2 = sy2[i];
            float areaA = (ax2 - ax1) * (ay2 - ay1);
            for (int t = i + 1 + tid; t < M; t += T) {
                if (skeep[t]) {
                    float x1 = fmaxf(ax1, sx1[t]), y1 = fmaxf(ay1, sy1[t]);
                    float x2 = fminf(ax2, sx2[t]), y2 = fminf(ay2, sy2[t]);
                    float inter = fmaxf(x2 - x1, 0.0f) * fmaxf(y2 - y1, 0.0f);
                    float areaB = (sx2[t] - sx1[t]) * (sy2[t] - sy1[t]);
                    float uni = areaA + areaB - inter;
                    if (inter / uni > NMS_T) skeep[t] = 0;
                }
            }
        }
        __syncthreads();
    }

    // compose outputs for all cells owned by this (b,cls) block
    for (int t = tid; t < M; t += T) {
        int n = (int)(sk[t] & 0xFFFFFFFFULL);
        int idx = b * Nn + n;
        bool k = skeep[t] != 0;
        float s = __uint_as_float(~(unsigned)(sk[t] >> 32));
        out[idx * 5 + 0] = k ? sx1[t] : 0.0f;
        out[idx * 5 + 1] = k ? sy1[t] : 0.0f;
        out[idx * 5 + 2] = k ? sx2[t] : 0.0f;
        out[idx * 5 + 3] = k ? sy2[t] : 0.0f;
        out[idx * 5 + 4] = k ? s : 0.0f;
        out[Bn * Nn * 6 + idx] = k ? 1.0f : 0.0f;  // keep region
    }
}

// ---------------- launch -----------------------------------------------------
extern "C" void kernel_launch(void* const* d_in, const int* in_sizes, int n_in,
                              void* d_out, int out_size)
{
    const float* feat = (const float*)d_in[0];
    const float* wo   = (const float*)d_in[1];
    const float* bo   = (const float*)d_in[2];
    const float* wc   = (const float*)d_in[3];
    const float* bc   = (const float*)d_in[4];
    const float* wr   = (const float*)d_in[5];
    const float* br   = (const float*)d_in[6];
    float* out = (float*)d_out;

    size_t smem = (size_t)(Cn * 26 + 32) * sizeof(float);  // ~53.4 KB > 48 KB
    cudaFuncSetAttribute(head_kernel,
                         cudaFuncAttributeMaxDynamicSharedMemorySize, (int)smem);

    head_kernel<<<400, 128, smem>>>(feat, wo, bo, wc, bc, wr, br, out);
    nms_kernel<<<dim3(NCn, Bn), 256>>>(out);
}